// round 1
// baseline (speedup 1.0000x reference)
#include <cuda_runtime.h>
#include <math.h>

// Problem constants (fixed by the reference)
#define Bz   32
#define Lz   12
#define Nz   2000
#define Cz   2
#define Hz   64
#define Ez   32000
#define Sz   2
#define CATz 66            // C + H
#define NM   5             // S*K + 1
#define FW   (CATz * NM)   // 330
#define ROWS (Bz * Nz)     // 64000
#define OUT_MAIN (Bz * Lz * Nz * Hz)

// Persistent scratch (static device globals; no allocation at runtime)
__device__ float g_h[ROWS * Hz];        // current hidden state  (B,N,H)
__device__ float g_feat[ROWS * FW];     // diffusion features    (B*N, 330)
__device__ float g_gate[ROWS * 2 * Hz]; // r (cols 0..63), u (cols 64..127)
__device__ float g_c[ROWS * Hz];        // candidate

// ---------------------------------------------------------------------------
__global__ void copy_h0(const float* __restrict__ h0) {
    int i = blockIdx.x * 256 + threadIdx.x;
    if (i < ROWS * Hz) g_h[i] = h0[i];
}

// Build the feat matrix for one diffusion conv.
// Block m layout in columns: m=0 -> v, m=1 -> s0·x1 (init 0), m=2 -> s0·x2 (init -v),
//                            m=3 -> s1·x1 (init 0), m=4 -> s1·x2 (init -v)
// cand==0: v = [h, x_t]; cand==1: v = [r*h, x_t]
__global__ void build_feat(const float* __restrict__ x, int t, int cand) {
    int row = blockIdx.x;          // 0..ROWS-1  (= b*N + n)
    int col = threadIdx.x;         // 0..329
    if (col >= FW) return;
    int m = col / CATz;
    int j = col - m * CATz;
    float v;
    if (j < Hz) {
        float hv = g_h[row * Hz + j];
        if (cand) hv *= g_gate[row * (2 * Hz) + j];   // r gate
        v = hv;
    } else {
        int b = row / Nz, n = row - b * Nz;
        v = x[((b * Lz + t) * Nz + n) * Cz + (j - Hz)];
    }
    float o;
    if (m == 0)            o = v;
    else if (m == 1 || m == 3) o = 0.0f;
    else                   o = -v;
    g_feat[row * FW + col] = o;
}

// Sparse scatter for the diffusion recurrence (both supports in one launch).
// stage 1: x1 += w * v[src]        (into blocks 1/3, which start at 0)
// stage 2: x2 += 2*w * x1[src]     (into blocks 2/4, which start at -v)
__global__ void spmm_scatter(const int* __restrict__ As_idx,
                             const float* __restrict__ As_w, int stage) {
    int p = blockIdx.x * blockDim.y + threadIdx.y;   // (s,b,e) pair
    if (p >= Sz * Bz * Ez) return;
    int f = threadIdx.x;                             // 0..65
    int s = p / (Bz * Ez);
    int r = p - s * (Bz * Ez);
    int b = r / Ez;
    int e = r - b * Ez;
    int src = As_idx[(s * 2 + 0) * Ez + e];
    int dst = As_idx[(s * 2 + 1) * Ez + e];
    float wv = As_w[s * Ez + e];
    int in_off, out_off;
    float scale;
    if (stage == 1) { in_off = 0;                  out_off = (1 + s * 2) * CATz; scale = 1.0f; }
    else            { in_off = (1 + s * 2) * CATz; out_off = (2 + s * 2) * CATz; scale = 2.0f; }
    float val = g_feat[(b * Nz + src) * FW + in_off + f];
    atomicAdd(&g_feat[(b * Nz + dst) * FW + out_off + f], scale * wv * val);
}

// Tiled SGEMM: out = act(g_feat @ W + bias).  ACT 0: sigmoid -> g_gate, ACT 1: tanh -> g_c
template <int ACT>
__global__ void gemm_bias_act(const float* __restrict__ W,
                              const float* __restrict__ bias, int Nout) {
    __shared__ float As[64][33];
    __shared__ float Bs[32][64];
    int tx = threadIdx.x & 15, ty = threadIdx.x >> 4;
    int row0 = blockIdx.y * 64;
    int col0 = blockIdx.x * 64;
    float acc[4][4];
#pragma unroll
    for (int i = 0; i < 4; i++)
#pragma unroll
        for (int j = 0; j < 4; j++) acc[i][j] = 0.0f;

    for (int k0 = 0; k0 < FW; k0 += 32) {
#pragma unroll
        for (int i = 0; i < 8; i++) {
            int idx = threadIdx.x + i * 256;
            int r = idx >> 5, c = idx & 31;
            As[r][c] = (k0 + c < FW) ? g_feat[(row0 + r) * FW + k0 + c] : 0.0f;
        }
#pragma unroll
        for (int i = 0; i < 8; i++) {
            int idx = threadIdx.x + i * 256;
            int r = idx >> 6, c = idx & 63;
            Bs[r][c] = (k0 + r < FW) ? W[(k0 + r) * Nout + col0 + c] : 0.0f;
        }
        __syncthreads();
#pragma unroll
        for (int k = 0; k < 32; k++) {
            float ra[4], rb[4];
#pragma unroll
            for (int i = 0; i < 4; i++) ra[i] = As[ty * 4 + i][k];
#pragma unroll
            for (int j = 0; j < 4; j++) rb[j] = Bs[k][tx * 4 + j];
#pragma unroll
            for (int i = 0; i < 4; i++)
#pragma unroll
                for (int j = 0; j < 4; j++) acc[i][j] += ra[i] * rb[j];
        }
        __syncthreads();
    }
#pragma unroll
    for (int i = 0; i < 4; i++)
#pragma unroll
        for (int j = 0; j < 4; j++) {
            float v = acc[i][j] + bias[col0 + tx * 4 + j];
            if (ACT == 0) {
                v = 1.0f / (1.0f + __expf(-v));
                g_gate[(row0 + ty * 4 + i) * Nout + col0 + tx * 4 + j] = v;
            } else {
                v = tanhf(v);
                g_c[(row0 + ty * 4 + i) * Nout + col0 + tx * 4 + j] = v;
            }
        }
}

// GRU state update + write output slice; also writes h_n tail on last step.
__global__ void h_update(float* __restrict__ out, int t, int write_tail) {
    int i = blockIdx.x * 256 + threadIdx.x;
    if (i >= ROWS * Hz) return;
    int row = i >> 6, f = i & 63;
    float u = g_gate[row * (2 * Hz) + Hz + f];
    float hn = u * g_h[i] + (1.0f - u) * g_c[i];
    g_h[i] = hn;
    int b = row / Nz, n = row - b * Nz;
    out[((b * Lz + t) * Nz + n) * Hz + f] = hn;
    if (write_tail) out[OUT_MAIN + i] = hn;
}

// ---------------------------------------------------------------------------
extern "C" void kernel_launch(void* const* d_in, const int* in_sizes, int n_in,
                              void* d_out, int out_size) {
    (void)in_sizes; (void)n_in;
    const float* x      = (const float*)d_in[0];
    const int*   As_idx = (const int*)  d_in[1];
    const float* As_w   = (const float*)d_in[2];
    const float* h0     = (const float*)d_in[3];
    const float* Wg     = (const float*)d_in[4];
    const float* bg     = (const float*)d_in[5];
    const float* Wc     = (const float*)d_in[6];
    const float* bc     = (const float*)d_in[7];
    float* out = (float*)d_out;
    int write_tail = (out_size >= OUT_MAIN + ROWS * Hz) ? 1 : 0;

    copy_h0<<<(ROWS * Hz + 255) / 256, 256>>>(h0);

    dim3 sb(66, 4);
    int sgrid = (Sz * Bz * Ez + 3) / 4;

    for (int t = 0; t < Lz; t++) {
        // --- gate conv ---
        build_feat<<<ROWS, 330>>>(x, t, 0);
        spmm_scatter<<<sgrid, sb>>>(As_idx, As_w, 1);
        spmm_scatter<<<sgrid, sb>>>(As_idx, As_w, 2);
        gemm_bias_act<0><<<dim3(2, ROWS / 64), 256>>>(Wg, bg, 2 * Hz);
        // --- candidate conv ---
        build_feat<<<ROWS, 330>>>(x, t, 1);
        spmm_scatter<<<sgrid, sb>>>(As_idx, As_w, 1);
        spmm_scatter<<<sgrid, sb>>>(As_idx, As_w, 2);
        gemm_bias_act<1><<<dim3(1, ROWS / 64), 256>>>(Wc, bc, Hz);
        // --- GRU update ---
        h_update<<<(ROWS * Hz + 255) / 256, 256>>>(out, t, (t == Lz - 1) ? write_tail : 0);
    }
}

// round 2
// speedup vs baseline: 3.2955x; 3.2955x over previous
#include <cuda_runtime.h>
#include <math.h>

// Problem constants (fixed by the reference)
#define Bz   32
#define Lz   12
#define Nz   2000
#define Cz   2
#define Hz   64
#define Ez   32000
#define Sz   2
#define CATz 66            // C + H
#define NM   5             // S*K + 1
#define FW   (CATz * NM)   // 330
#define ROWS (Bz * Nz)     // 64000
#define OUT_MAIN (Bz * Lz * Nz * Hz)

// Persistent scratch (static device globals; no allocation at runtime)
__device__ float g_h[ROWS * Hz];        // current hidden state  (B,N,H)
__device__ float g_feat[ROWS * FW];     // diffusion features    (B*N, 330)
__device__ float g_gate[ROWS * 2 * Hz]; // r (cols 0..63), u (cols 64..127)
__device__ float g_c[ROWS * Hz];        // candidate

// CSR (edges grouped by dst), built once per launch
__device__ int   g_cnt[Sz][Nz];
__device__ int   g_rowptr[Sz][Nz + 1];
__device__ int   g_srcs[Sz][Ez];
__device__ float g_ws[Sz][Ez];

// ---------------------------------------------------------------------------
__global__ void copy_h0(const float* __restrict__ h0) {
    int i = blockIdx.x * 256 + threadIdx.x;
    if (i < ROWS * Hz) g_h[i] = h0[i];
}

__global__ void csr_zero() {
    int i = blockIdx.x * 256 + threadIdx.x;
    if (i < Sz * Nz) ((int*)g_cnt)[i] = 0;
}

__global__ void csr_count(const int* __restrict__ As_idx) {
    int i = blockIdx.x * 256 + threadIdx.x;
    if (i >= Sz * Ez) return;
    int s = i / Ez, e = i - s * Ez;
    int dst = As_idx[(s * 2 + 1) * Ez + e];
    atomicAdd(&g_cnt[s][dst], 1);
}

// One block per support: exclusive scan of 2000 counts (pairs per thread + Hillis-Steele)
__global__ void csr_scan() {
    int s = blockIdx.x;
    __shared__ int arr[1024];
    int t = threadIdx.x;
    int a = 0, b = 0;
    if (2 * t < Nz)     a = g_cnt[s][2 * t];
    if (2 * t + 1 < Nz) b = g_cnt[s][2 * t + 1];
    arr[t] = a + b;
    __syncthreads();
    for (int off = 1; off < 1024; off <<= 1) {
        int v = arr[t];
        int add = (t >= off) ? arr[t - off] : 0;
        __syncthreads();
        arr[t] = v + add;
        __syncthreads();
    }
    int incl = arr[t];
    int excl = incl - (a + b);
    if (2 * t < Nz)     { g_rowptr[s][2 * t] = excl;     g_cnt[s][2 * t] = 0; }
    if (2 * t + 1 < Nz) { g_rowptr[s][2 * t + 1] = excl + a; g_cnt[s][2 * t + 1] = 0; }
    if (t == 1023) g_rowptr[s][Nz] = arr[1023];
}

__global__ void csr_fill(const int* __restrict__ As_idx, const float* __restrict__ As_w) {
    int i = blockIdx.x * 256 + threadIdx.x;
    if (i >= Sz * Ez) return;
    int s = i / Ez, e = i - s * Ez;
    int src = As_idx[(s * 2 + 0) * Ez + e];
    int dst = As_idx[(s * 2 + 1) * Ez + e];
    int pos = g_rowptr[s][dst] + atomicAdd(&g_cnt[s][dst], 1);
    g_srcs[s][pos] = src;
    g_ws[s][pos]   = As_w[s * Ez + e];
}

// Write only block 0 (v = [h,x] or [r*h,x]) of the feat matrix.
__global__ void build_feat(const float* __restrict__ x, int t, int cand) {
    int i = blockIdx.x * 256 + threadIdx.x;
    if (i >= ROWS * CATz) return;
    int row = i / CATz, j = i - row * CATz;
    float v;
    if (j < Hz) {
        v = g_h[row * Hz + j];
        if (cand) v *= g_gate[row * (2 * Hz) + j];
    } else {
        int b = row / Nz, n = row - b * Nz;
        v = x[((b * Lz + t) * Nz + n) * Cz + (j - Hz)];
    }
    g_feat[(long)row * FW + j] = v;
}

// Gather-based diffusion step. One warp per (s,b,n) row; lanes cover 66 features.
// STAGE 1: x1 = A v            (in: block 0,     out: block 1+2s)
// STAGE 2: x2 = 2 A x1 - v     (in: block 1+2s,  out: block 2+2s)
template <int STAGE>
__global__ void spmm_gather() {
    int lane = threadIdx.x & 31;
    int wrow = threadIdx.x >> 5;               // 0..7
    int p = blockIdx.x * 8 + wrow;             // (s,b,n) row id
    if (p >= Sz * Bz * Nz) return;
    int s = p / (Bz * Nz);
    int r = p - s * (Bz * Nz);
    int b = r / Nz;
    int n = r - b * Nz;

    int in_off = (STAGE == 1) ? 0 : (1 + 2 * s) * CATz;
    const float* fin = g_feat + (long)(b * Nz) * FW + in_off;
    int beg = g_rowptr[s][n], end = g_rowptr[s][n + 1];

    float a0 = 0.f, a1 = 0.f, a2 = 0.f;
    for (int e = beg; e < end; e++) {
        int src  = g_srcs[s][e];
        float w  = g_ws[s][e];
        const float* vp = fin + (long)src * FW;
        a0 += w * vp[lane];
        a1 += w * vp[lane + 32];
        if (lane < 2) a2 += w * vp[lane + 64];
    }

    long row = (long)(b * Nz + n);
    float* fo = g_feat + row * FW + ((STAGE == 1 ? 1 : 2) + 2 * s) * CATz;
    if (STAGE == 1) {
        fo[lane] = a0; fo[lane + 32] = a1;
        if (lane < 2) fo[lane + 64] = a2;
    } else {
        const float* v0 = g_feat + row * FW;
        fo[lane]      = 2.f * a0 - v0[lane];
        fo[lane + 32] = 2.f * a1 - v0[lane + 32];
        if (lane < 2) fo[lane + 64] = 2.f * a2 - v0[lane + 64];
    }
}

// Tiled SGEMM: out = act(g_feat @ W + bias).  ACT 0: sigmoid -> g_gate, ACT 1: tanh -> g_c
template <int ACT>
__global__ void gemm_bias_act(const float* __restrict__ W,
                              const float* __restrict__ bias, int Nout) {
    __shared__ float As[64][33];
    __shared__ float Bs[32][64];
    int tx = threadIdx.x & 15, ty = threadIdx.x >> 4;
    int row0 = blockIdx.y * 64;
    int col0 = blockIdx.x * 64;
    float acc[4][4];
#pragma unroll
    for (int i = 0; i < 4; i++)
#pragma unroll
        for (int j = 0; j < 4; j++) acc[i][j] = 0.0f;

    for (int k0 = 0; k0 < FW; k0 += 32) {
#pragma unroll
        for (int i = 0; i < 8; i++) {
            int idx = threadIdx.x + i * 256;
            int r = idx >> 5, c = idx & 31;
            As[r][c] = (k0 + c < FW) ? g_feat[(long)(row0 + r) * FW + k0 + c] : 0.0f;
        }
#pragma unroll
        for (int i = 0; i < 8; i++) {
            int idx = threadIdx.x + i * 256;
            int r = idx >> 6, c = idx & 63;
            Bs[r][c] = (k0 + r < FW) ? W[(k0 + r) * Nout + col0 + c] : 0.0f;
        }
        __syncthreads();
#pragma unroll
        for (int k = 0; k < 32; k++) {
            float ra[4], rb[4];
#pragma unroll
            for (int i = 0; i < 4; i++) ra[i] = As[ty * 4 + i][k];
#pragma unroll
            for (int j = 0; j < 4; j++) rb[j] = Bs[k][tx * 4 + j];
#pragma unroll
            for (int i = 0; i < 4; i++)
#pragma unroll
                for (int j = 0; j < 4; j++) acc[i][j] += ra[i] * rb[j];
        }
        __syncthreads();
    }
#pragma unroll
    for (int i = 0; i < 4; i++)
#pragma unroll
        for (int j = 0; j < 4; j++) {
            float v = acc[i][j] + bias[col0 + tx * 4 + j];
            if (ACT == 0) {
                v = 1.0f / (1.0f + __expf(-v));
                g_gate[(row0 + ty * 4 + i) * Nout + col0 + tx * 4 + j] = v;
            } else {
                v = tanhf(v);
                g_c[(row0 + ty * 4 + i) * Nout + col0 + tx * 4 + j] = v;
            }
        }
}

// GRU state update + write output slice; also writes h_n tail on last step.
__global__ void h_update(float* __restrict__ out, int t, int write_tail) {
    int i = blockIdx.x * 256 + threadIdx.x;
    if (i >= ROWS * Hz) return;
    int row = i >> 6, f = i & 63;
    float u = g_gate[row * (2 * Hz) + Hz + f];
    float hn = u * g_h[i] + (1.0f - u) * g_c[i];
    g_h[i] = hn;
    int b = row / Nz, n = row - b * Nz;
    out[((b * Lz + t) * Nz + n) * Hz + f] = hn;
    if (write_tail) out[OUT_MAIN + i] = hn;
}

// ---------------------------------------------------------------------------
extern "C" void kernel_launch(void* const* d_in, const int* in_sizes, int n_in,
                              void* d_out, int out_size) {
    (void)in_sizes; (void)n_in;
    const float* x      = (const float*)d_in[0];
    const int*   As_idx = (const int*)  d_in[1];
    const float* As_w   = (const float*)d_in[2];
    const float* h0     = (const float*)d_in[3];
    const float* Wg     = (const float*)d_in[4];
    const float* bg     = (const float*)d_in[5];
    const float* Wc     = (const float*)d_in[6];
    const float* bc     = (const float*)d_in[7];
    float* out = (float*)d_out;
    int write_tail = (out_size >= OUT_MAIN + ROWS * Hz) ? 1 : 0;

    copy_h0<<<(ROWS * Hz + 255) / 256, 256>>>(h0);

    // CSR build (per replay; cheap)
    csr_zero<<<(Sz * Nz + 255) / 256, 256>>>();
    csr_count<<<(Sz * Ez + 255) / 256, 256>>>(As_idx);
    csr_scan<<<Sz, 1024>>>();
    csr_fill<<<(Sz * Ez + 255) / 256, 256>>>(As_idx, As_w);

    int bf_grid = (ROWS * CATz + 255) / 256;
    int gg_grid = (Sz * Bz * Nz + 7) / 8;

    for (int t = 0; t < Lz; t++) {
        // --- gate conv ---
        build_feat<<<bf_grid, 256>>>(x, t, 0);
        spmm_gather<1><<<gg_grid, 256>>>();
        spmm_gather<2><<<gg_grid, 256>>>();
        gemm_bias_act<0><<<dim3(2, ROWS / 64), 256>>>(Wg, bg, 2 * Hz);
        // --- candidate conv ---
        build_feat<<<bf_grid, 256>>>(x, t, 1);
        spmm_gather<1><<<gg_grid, 256>>>();
        spmm_gather<2><<<gg_grid, 256>>>();
        gemm_bias_act<1><<<dim3(1, ROWS / 64), 256>>>(Wc, bc, Hz);
        // --- GRU update ---
        h_update<<<(ROWS * Hz + 255) / 256, 256>>>(out, t, (t == Lz - 1) ? write_tail : 0);
    }
}